// round 2
// baseline (speedup 1.0000x reference)
#include <cuda_runtime.h>
#include <cuda_bf16.h>
#include <cstdint>

// Problem constants (match reference_code)
#define NV       1000000
#define NE       3000000
#define IMG_H    1024
#define IMG_W    1024
#define HW       (IMG_H * IMG_W)       // 1048576
#define MAX_DEPTH 10.0f
#define CREGU    2000.0f

// ---------------- scratch (device globals; no allocation allowed) ----------
__device__ float  g_depth[HW];        // 4 MB   scatter-min target
__device__ float  g_dv[3 * NV];       // 12 MB  vertices - vertices_ref
__device__ float  g_neigh[3 * NV];    // 12 MB  segment_sum(dv[dst], src)
__device__ float  g_deg[NV];          // 4 MB   segment_sum(ones, src)
__device__ double g_sums[3];          // vertex component sums (for mean)
__device__ double g_acc;              // total energy accumulator

// ---------------- K1: init scratch + compute dv ----------------------------
__global__ void k_init(const float* __restrict__ verts,
                       const float* __restrict__ vref) {
    int i = blockIdx.x * blockDim.x + threadIdx.x;
    if (i < 3 * NV) {
        g_neigh[i] = 0.0f;
        g_dv[i]    = verts[i] - vref[i];
    }
    if (i < NV) g_deg[i] = 0.0f;
    if (i < HW) g_depth[i] = MAX_DEPTH;
    if (i == 0) {
        g_sums[0] = 0.0; g_sums[1] = 0.0; g_sums[2] = 0.0;
        g_acc = 0.0;
    }
}

// ---------------- block reduce helper (double) ------------------------------
__device__ __forceinline__ double block_reduce_d(double v) {
    __shared__ double sh[256];
    int t = threadIdx.x;
    sh[t] = v;
    __syncthreads();
    for (int s = blockDim.x >> 1; s > 0; s >>= 1) {
        if (t < s) sh[t] += sh[t + s];
        __syncthreads();
    }
    return sh[0];
}

// ---------------- K2: vertex mean (component sums) --------------------------
__global__ void k_mean(const float* __restrict__ verts) {
    double sx = 0.0, sy = 0.0, sz = 0.0;
    for (int i = blockIdx.x * blockDim.x + threadIdx.x; i < NV;
         i += gridDim.x * blockDim.x) {
        sx += (double)verts[3 * i + 0];
        sy += (double)verts[3 * i + 1];
        sz += (double)verts[3 * i + 2];
    }
    double bx = block_reduce_d(sx);
    __syncthreads();
    double by = block_reduce_d(sy);
    __syncthreads();
    double bz = block_reduce_d(sz);
    if (threadIdx.x == 0) {
        atomicAdd(&g_sums[0], bx);
        atomicAdd(&g_sums[1], by);
        atomicAdd(&g_sums[2], bz);
    }
}

// ---------------- K3: transform + project + scatter-min depth ---------------
__global__ void k_proj(const float* __restrict__ verts,
                       const float* __restrict__ quat,
                       const float* __restrict__ trans,
                       const float* __restrict__ intr,
                       const float* __restrict__ extr) {
    int i = blockIdx.x * blockDim.x + threadIdx.x;
    if (i >= NV) return;

    float qx = quat[0], qy = quat[1], qz = quat[2], qw = quat[3];
    float qn = 1.0f / sqrtf(qx * qx + qy * qy + qz * qz + qw * qw);
    qx *= qn; qy *= qn; qz *= qn; qw *= qn;

    float mx = (float)(g_sums[0] / (double)NV);
    float my = (float)(g_sums[1] / (double)NV);
    float mz = (float)(g_sums[2] / (double)NV);

    float vx = verts[3 * i + 0] - mx;
    float vy = verts[3 * i + 1] - my;
    float vz = verts[3 * i + 2] - mz;

    // qrot: v + 2*(w*uv + uuv), uv = qv x v, uuv = qv x uv
    float uvx = qy * vz - qz * vy;
    float uvy = qz * vx - qx * vz;
    float uvz = qx * vy - qy * vx;
    float uuvx = qy * uvz - qz * uvy;
    float uuvy = qz * uvx - qx * uvz;
    float uuvz = qx * uvy - qy * uvx;
    float tx = vx + 2.0f * (qw * uvx + uuvx) + trans[0];
    float ty = vy + 2.0f * (qw * uvy + uuvy) + trans[1];
    float tz = vz + 2.0f * (qw * uvz + uuvz) + trans[2];

    // p_cam = E[:, :3] @ v_t + E[:, 3]   (extr row-major 3x4)
    float p0 = extr[0] * tx + extr[1] * ty + extr[2]  * tz + extr[3];
    float p1 = extr[4] * tx + extr[5] * ty + extr[6]  * tz + extr[7];
    float p2 = extr[8] * tx + extr[9] * ty + extr[10] * tz + extr[11];

    // proj = K @ p_cam (intr row-major 3x3)
    float pr0 = intr[0] * p0 + intr[1] * p1 + intr[2] * p2;
    float pr1 = intr[3] * p0 + intr[4] * p1 + intr[5] * p2;
    float pr2 = intr[6] * p0 + intr[7] * p1 + intr[8] * p2;

    float u = pr0 / pr2;
    float v = pr1 / pr2;

    float fx = rintf(u);                  // round half to even == jnp.round
    float fy = rintf(v);
    fx = fminf(fmaxf(fx, 0.0f), (float)(IMG_W - 1));
    fy = fminf(fmaxf(fy, 0.0f), (float)(IMG_H - 1));
    int xi = (int)fx;
    int yi = (int)fy;
    int flat = yi * IMG_W + xi;

    float zval = (p2 > 0.0f) ? p2 : MAX_DEPTH;   // DEPTH_SCALE = 1
    // zval > 0 always, so int-bitpattern min == float min
    atomicMin((int*)&g_depth[flat], __float_as_int(zval));
}

// ---------------- K4: edge accumulation (deg, neigh) ------------------------
// edges are int32 on device (JAX canonicalizes int64 -> int32 without x64)
__global__ void k_edge(const int* __restrict__ edges) {
    int e = blockIdx.x * blockDim.x + threadIdx.x;
    if (e >= NE) return;
    int2 p = ((const int2*)edges)[e];     // (src, dst), 8B coalesced
    int s = p.x;
    int d = p.y;
    float dx = g_dv[3 * d + 0];
    float dy = g_dv[3 * d + 1];
    float dz = g_dv[3 * d + 2];
    atomicAdd(&g_neigh[3 * s + 0], dx);
    atomicAdd(&g_neigh[3 * s + 1], dy);
    atomicAdd(&g_neigh[3 * s + 2], dz);
    atomicAdd(&g_deg[s], 1.0f);
}

// ---------------- K5: energy (data + rigid) ---------------------------------
__global__ void k_energy(const float* __restrict__ hand) {
    double local = 0.0;
    for (int i = blockIdx.x * blockDim.x + threadIdx.x; i < HW;
         i += gridDim.x * blockDim.x) {
        float diff = g_depth[i] - hand[i];
        local += (double)(diff * diff);
        if (i < NV) {
            float dg = g_deg[i];
            float lx = dg * g_dv[3 * i + 0] - g_neigh[3 * i + 0];
            float ly = dg * g_dv[3 * i + 1] - g_neigh[3 * i + 1];
            float lz = dg * g_dv[3 * i + 2] - g_neigh[3 * i + 2];
            local += (double)CREGU * ((double)(lx * lx) + (double)(ly * ly) +
                                      (double)(lz * lz));
        }
    }
    double b = block_reduce_d(local);
    if (threadIdx.x == 0) atomicAdd(&g_acc, b);
}

// ---------------- K6: finalize ----------------------------------------------
__global__ void k_final(float* __restrict__ out) {
    out[0] = (float)g_acc;
}

// ---------------- launch -----------------------------------------------------
extern "C" void kernel_launch(void* const* d_in, const int* in_sizes, int n_in,
                              void* d_out, int out_size) {
    const float* verts = (const float*)d_in[0];
    const float* vref  = (const float*)d_in[1];
    const float* quat  = (const float*)d_in[2];
    const float* trans = (const float*)d_in[3];
    const float* hand  = (const float*)d_in[4];
    const float* intr  = (const float*)d_in[5];
    const float* extr  = (const float*)d_in[6];
    const int*   edges = (const int*)d_in[7];
    float* out = (float*)d_out;

    const int B = 256;
    k_init<<<(3 * NV + B - 1) / B, B>>>(verts, vref);
    k_mean<<<1024, B>>>(verts);
    k_proj<<<(NV + B - 1) / B, B>>>(verts, quat, trans, intr, extr);
    k_edge<<<(NE + B - 1) / B, B>>>(edges);
    k_energy<<<2048, B>>>(hand);
    k_final<<<1, 1>>>(out);
}

// round 4
// speedup vs baseline: 2.4623x; 2.4623x over previous
#include <cuda_runtime.h>
#include <cuda_bf16.h>
#include <cstdint>

// Problem constants (match reference_code)
#define NV       1000000
#define NE       3000000
#define IMG_H    1024
#define IMG_W    1024
#define HW       (IMG_H * IMG_W)       // 1048576
#define MAX_DEPTH 10.0f
#define CREGU    2000.0f

// ---------------- scratch (device globals; no allocation allowed) ----------
__device__ float  g_depth[HW];        // 4 MB    scatter-min target
__device__ float4 g_dv4[NV];          // 16 MB   {dvx, dvy, dvz, 0}
__device__ float4 g_neigh4[NV];       // 16 MB   {nx, ny, nz, deg}
__device__ double g_sums[3];          // vertex component sums (for mean)
__device__ double g_acc;              // total energy accumulator

// ---------------- K0: zero the small accumulators ---------------------------
__global__ void k_zero() {
    if (threadIdx.x == 0) {
        g_sums[0] = 0.0; g_sums[1] = 0.0; g_sums[2] = 0.0;
        g_acc = 0.0;
    }
}

// ---------------- float block reduce (shared) --------------------------------
__device__ __forceinline__ float block_reduce_f(float v) {
    __shared__ float sh[256];
    int t = threadIdx.x;
    sh[t] = v;
    __syncthreads();
    for (int s = blockDim.x >> 1; s > 32; s >>= 1) {
        if (t < s) sh[t] += sh[t + s];
        __syncthreads();
    }
    if (t < 32) {
        float x = sh[t] + sh[t + 32];
        #pragma unroll
        for (int o = 16; o > 0; o >>= 1)
            x += __shfl_down_sync(0xFFFFFFFFu, x, o);
        if (t == 0) sh[0] = x;
    }
    __syncthreads();
    return sh[0];
}

// ---------------- K1: init scratch + dv4 + vertex mean partials --------------
// One thread per pixel (HW = 1048576); threads with i < NV also do vertex work.
__global__ void k_init(const float* __restrict__ verts,
                       const float* __restrict__ vref) {
    int i = blockIdx.x * blockDim.x + threadIdx.x;
    if (i < HW) g_depth[i] = MAX_DEPTH;

    float sx = 0.0f, sy = 0.0f, sz = 0.0f;
    if (i < NV) {
        float vx = verts[3 * i + 0];
        float vy = verts[3 * i + 1];
        float vz = verts[3 * i + 2];
        sx = vx; sy = vy; sz = vz;
        float4 dv;
        dv.x = vx - vref[3 * i + 0];
        dv.y = vy - vref[3 * i + 1];
        dv.z = vz - vref[3 * i + 2];
        dv.w = 0.0f;
        g_dv4[i]    = dv;
        g_neigh4[i] = make_float4(0.0f, 0.0f, 0.0f, 0.0f);
    }
    // block-level fp32 reduction; double atomics only once per block (cheap)
    float bx = block_reduce_f(sx);
    __syncthreads();
    float by = block_reduce_f(sy);
    __syncthreads();
    float bz = block_reduce_f(sz);
    if (threadIdx.x == 0) {
        atomicAdd(&g_sums[0], (double)bx);
        atomicAdd(&g_sums[1], (double)by);
        atomicAdd(&g_sums[2], (double)bz);
    }
}

// ---------------- K3: transform + project + scatter-min depth ---------------
__global__ void k_proj(const float* __restrict__ verts,
                       const float* __restrict__ quat,
                       const float* __restrict__ trans,
                       const float* __restrict__ intr,
                       const float* __restrict__ extr) {
    int i = blockIdx.x * blockDim.x + threadIdx.x;
    if (i >= NV) return;

    float qx = quat[0], qy = quat[1], qz = quat[2], qw = quat[3];
    float qn = 1.0f / sqrtf(qx * qx + qy * qy + qz * qz + qw * qw);
    qx *= qn; qy *= qn; qz *= qn; qw *= qn;

    float mx = (float)(g_sums[0] / (double)NV);
    float my = (float)(g_sums[1] / (double)NV);
    float mz = (float)(g_sums[2] / (double)NV);

    float vx = verts[3 * i + 0] - mx;
    float vy = verts[3 * i + 1] - my;
    float vz = verts[3 * i + 2] - mz;

    // qrot: v + 2*(w*uv + uuv), uv = qv x v, uuv = qv x uv
    float uvx = qy * vz - qz * vy;
    float uvy = qz * vx - qx * vz;
    float uvz = qx * vy - qy * vx;
    float uuvx = qy * uvz - qz * uvy;
    float uuvy = qz * uvx - qx * uvz;
    float uuvz = qx * uvy - qy * uvx;
    float tx = vx + 2.0f * (qw * uvx + uuvx) + trans[0];
    float ty = vy + 2.0f * (qw * uvy + uuvy) + trans[1];
    float tz = vz + 2.0f * (qw * uvz + uuvz) + trans[2];

    // p_cam = E[:, :3] @ v_t + E[:, 3]   (extr row-major 3x4)
    float p0 = extr[0] * tx + extr[1] * ty + extr[2]  * tz + extr[3];
    float p1 = extr[4] * tx + extr[5] * ty + extr[6]  * tz + extr[7];
    float p2 = extr[8] * tx + extr[9] * ty + extr[10] * tz + extr[11];

    // proj = K @ p_cam (intr row-major 3x3)
    float pr0 = intr[0] * p0 + intr[1] * p1 + intr[2] * p2;
    float pr1 = intr[3] * p0 + intr[4] * p1 + intr[5] * p2;
    float pr2 = intr[6] * p0 + intr[7] * p1 + intr[8] * p2;

    float u = pr0 / pr2;
    float v = pr1 / pr2;

    float fx = rintf(u);                  // round half to even == jnp.round
    float fy = rintf(v);
    fx = fminf(fmaxf(fx, 0.0f), (float)(IMG_W - 1));
    fy = fminf(fmaxf(fy, 0.0f), (float)(IMG_H - 1));
    int xi = (int)fx;
    int yi = (int)fy;
    int flat = yi * IMG_W + xi;

    float zval = (p2 > 0.0f) ? p2 : MAX_DEPTH;   // DEPTH_SCALE = 1
    // zval > 0 always, so int-bitpattern min == float min
    atomicMin((int*)&g_depth[flat], __float_as_int(zval));
}

// ---------------- K4: edge accumulation (single v4 reduction per edge) ------
__global__ void k_edge(const int2* __restrict__ edges) {
    int e = blockIdx.x * blockDim.x + threadIdx.x;
    if (e >= NE) return;
    int2 p = edges[e];                    // (src, dst), 8B coalesced
    float4 dv = g_dv4[p.y];               // one LDG.128 gather
    // {dvx, dvy, dvz, 1.0} accumulated into {nx, ny, nz, deg} in one RED.128
    asm volatile(
        "red.global.add.v4.f32 [%0], {%1, %2, %3, %4};"
        :: "l"(&g_neigh4[p.x]), "f"(dv.x), "f"(dv.y), "f"(dv.z), "f"(1.0f)
        : "memory");
}

// ---------------- K5: energy (data + rigid), fp32 accumulation ---------------
__global__ void k_energy(const float* __restrict__ hand) {
    int i = blockIdx.x * blockDim.x + threadIdx.x;
    float local = 0.0f;
    if (i < HW) {
        float diff = g_depth[i] - hand[i];     // depth in (0,10]; clip no-op
        local = diff * diff;
        if (i < NV) {
            float4 dv = g_dv4[i];
            float4 nb = g_neigh4[i];
            float dg = nb.w;
            float lx = dg * dv.x - nb.x;
            float ly = dg * dv.y - nb.y;
            float lz = dg * dv.z - nb.z;
            local += CREGU * (lx * lx + ly * ly + lz * lz);
        }
    }
    float b = block_reduce_f(local);
    if (threadIdx.x == 0) atomicAdd(&g_acc, (double)b);
}

// ---------------- K6: finalize ----------------------------------------------
__global__ void k_final(float* __restrict__ out) {
    out[0] = (float)g_acc;
}

// ---------------- launch -----------------------------------------------------
extern "C" void kernel_launch(void* const* d_in, const int* in_sizes, int n_in,
                              void* d_out, int out_size) {
    const float* verts = (const float*)d_in[0];
    const float* vref  = (const float*)d_in[1];
    const float* quat  = (const float*)d_in[2];
    const float* trans = (const float*)d_in[3];
    const float* hand  = (const float*)d_in[4];
    const float* intr  = (const float*)d_in[5];
    const float* extr  = (const float*)d_in[6];
    const int2*  edges = (const int2*)d_in[7];
    float* out = (float*)d_out;

    const int B = 256;
    k_zero<<<1, 32>>>();
    k_init<<<HW / B, B>>>(verts, vref);
    k_proj<<<(NV + B - 1) / B, B>>>(verts, quat, trans, intr, extr);
    k_edge<<<(NE + B - 1) / B, B>>>(edges);
    k_energy<<<HW / B, B>>>(hand);
    k_final<<<1, 1>>>(out);
}

// round 5
// speedup vs baseline: 2.8739x; 1.1672x over previous
#include <cuda_runtime.h>
#include <cuda_bf16.h>
#include <cstdint>

// Problem constants (match reference_code)
#define NV       1000000
#define NE       3000000
#define IMG_H    1024
#define IMG_W    1024
#define HW       (IMG_H * IMG_W)       // 1048576
#define MAX_DEPTH 10.0f
#define CREGU    2000.0f

// ---------------- scratch (device globals; no allocation allowed) ----------
__device__ float  g_depth[HW];        // 4 MB    scatter-min target
__device__ float4 g_dv4[NV];          // 16 MB   {dvx, dvy, dvz, 0}
__device__ float4 g_neigh4[NV];       // 16 MB   {nx, ny, nz, deg}
__device__ double g_sums[3];          // vertex component sums (for mean)
__device__ double g_acc;              // total energy accumulator

// ---------------- K0: zero the small accumulators ---------------------------
__global__ void k_zero() {
    if (threadIdx.x == 0) {
        g_sums[0] = 0.0; g_sums[1] = 0.0; g_sums[2] = 0.0;
        g_acc = 0.0;
    }
}

// ---------------- float block reduce (shared) --------------------------------
__device__ __forceinline__ float block_reduce_f(float v) {
    __shared__ float sh[256];
    int t = threadIdx.x;
    sh[t] = v;
    __syncthreads();
    for (int s = blockDim.x >> 1; s > 32; s >>= 1) {
        if (t < s) sh[t] += sh[t + s];
        __syncthreads();
    }
    if (t < 32) {
        float x = sh[t] + sh[t + 32];
        #pragma unroll
        for (int o = 16; o > 0; o >>= 1)
            x += __shfl_down_sync(0xFFFFFFFFu, x, o);
        if (t == 0) sh[0] = x;
    }
    __syncthreads();
    return sh[0];
}

// ---------------- K1: init scratch + dv4 + vertex mean partials --------------
// 262144 threads: each fills 4 depth pixels; threads < 250000 also handle
// 4 vertices (NV = 1M) with fully 128-bit memory ops.
__global__ void k_init(const float4* __restrict__ verts4,
                       const float4* __restrict__ vref4) {
    int i = blockIdx.x * blockDim.x + threadIdx.x;   // < 262144
    // depth fill: 4 pixels per thread, 128-bit store
    ((float4*)g_depth)[i] = make_float4(MAX_DEPTH, MAX_DEPTH, MAX_DEPTH, MAX_DEPTH);

    float sx = 0.0f, sy = 0.0f, sz = 0.0f;
    if (i < NV / 4) {
        // 4 vertices = 12 floats = 3 float4 loads
        float4 a = verts4[3 * i + 0];   // v0.x v0.y v0.z v1.x
        float4 b = verts4[3 * i + 1];   // v1.y v1.z v2.x v2.y
        float4 c = verts4[3 * i + 2];   // v2.z v3.x v3.y v3.z
        float4 ra = vref4[3 * i + 0];
        float4 rb = vref4[3 * i + 1];
        float4 rc = vref4[3 * i + 2];

        sx = a.x + a.w + b.z + c.y;
        sy = a.y + b.x + b.w + c.z;
        sz = a.z + b.y + c.x + c.w;

        g_dv4[4 * i + 0] = make_float4(a.x - ra.x, a.y - ra.y, a.z - ra.z, 0.0f);
        g_dv4[4 * i + 1] = make_float4(a.w - ra.w, b.x - rb.x, b.y - rb.y, 0.0f);
        g_dv4[4 * i + 2] = make_float4(b.z - rb.z, b.w - rb.w, c.x - rc.x, 0.0f);
        g_dv4[4 * i + 3] = make_float4(c.y - rc.y, c.z - rc.z, c.w - rc.w, 0.0f);
        float4 z4 = make_float4(0.0f, 0.0f, 0.0f, 0.0f);
        g_neigh4[4 * i + 0] = z4;
        g_neigh4[4 * i + 1] = z4;
        g_neigh4[4 * i + 2] = z4;
        g_neigh4[4 * i + 3] = z4;
    }
    float bx = block_reduce_f(sx);
    __syncthreads();
    float by = block_reduce_f(sy);
    __syncthreads();
    float bz = block_reduce_f(sz);
    if (threadIdx.x == 0) {
        atomicAdd(&g_sums[0], (double)bx);
        atomicAdd(&g_sums[1], (double)by);
        atomicAdd(&g_sums[2], (double)bz);
    }
}

// ---------------- K3: transform + project + scatter-min depth ---------------
// 4 vertices per thread, 128-bit loads.
__global__ void k_proj(const float4* __restrict__ verts4,
                       const float* __restrict__ quat,
                       const float* __restrict__ trans,
                       const float* __restrict__ intr,
                       const float* __restrict__ extr) {
    int i = blockIdx.x * blockDim.x + threadIdx.x;   // < 250000
    if (i >= NV / 4) return;

    float qx = quat[0], qy = quat[1], qz = quat[2], qw = quat[3];
    float qn = 1.0f / sqrtf(qx * qx + qy * qy + qz * qz + qw * qw);
    qx *= qn; qy *= qn; qz *= qn; qw *= qn;

    float mx = (float)(g_sums[0] / (double)NV);
    float my = (float)(g_sums[1] / (double)NV);
    float mz = (float)(g_sums[2] / (double)NV);

    float4 a = verts4[3 * i + 0];
    float4 b = verts4[3 * i + 1];
    float4 c = verts4[3 * i + 2];
    float vxs[4] = {a.x, a.w, b.z, c.y};
    float vys[4] = {a.y, b.x, b.w, c.z};
    float vzs[4] = {a.z, b.y, c.x, c.w};

    #pragma unroll
    for (int k = 0; k < 4; k++) {
        float vx = vxs[k] - mx;
        float vy = vys[k] - my;
        float vz = vzs[k] - mz;

        // qrot: v + 2*(w*uv + uuv), uv = qv x v, uuv = qv x uv
        float uvx = qy * vz - qz * vy;
        float uvy = qz * vx - qx * vz;
        float uvz = qx * vy - qy * vx;
        float uuvx = qy * uvz - qz * uvy;
        float uuvy = qz * uvx - qx * uvz;
        float uuvz = qx * uvy - qy * uvx;
        float tx = vx + 2.0f * (qw * uvx + uuvx) + trans[0];
        float ty = vy + 2.0f * (qw * uvy + uuvy) + trans[1];
        float tz = vz + 2.0f * (qw * uvz + uuvz) + trans[2];

        // p_cam = E[:, :3] @ v_t + E[:, 3]   (extr row-major 3x4)
        float p0 = extr[0] * tx + extr[1] * ty + extr[2]  * tz + extr[3];
        float p1 = extr[4] * tx + extr[5] * ty + extr[6]  * tz + extr[7];
        float p2 = extr[8] * tx + extr[9] * ty + extr[10] * tz + extr[11];

        // proj = K @ p_cam (intr row-major 3x3)
        float pr0 = intr[0] * p0 + intr[1] * p1 + intr[2] * p2;
        float pr1 = intr[3] * p0 + intr[4] * p1 + intr[5] * p2;
        float pr2 = intr[6] * p0 + intr[7] * p1 + intr[8] * p2;

        float u = pr0 / pr2;
        float v = pr1 / pr2;

        float fx = rintf(u);                  // round half to even == jnp.round
        float fy = rintf(v);
        fx = fminf(fmaxf(fx, 0.0f), (float)(IMG_W - 1));
        fy = fminf(fmaxf(fy, 0.0f), (float)(IMG_H - 1));
        int xi = (int)fx;
        int yi = (int)fy;
        int flat = yi * IMG_W + xi;

        float zval = (p2 > 0.0f) ? p2 : MAX_DEPTH;   // DEPTH_SCALE = 1
        // zval > 0 always, so int-bitpattern min == float min
        atomicMin((int*)&g_depth[flat], __float_as_int(zval));
    }
}

// ---------------- K4: edge accumulation (2 edges/thread, v4 reductions) -----
__global__ void k_edge(const int4* __restrict__ edges2) {
    int e = blockIdx.x * blockDim.x + threadIdx.x;   // < NE/2
    if (e >= NE / 2) return;
    int4 p = edges2[e];                   // (s0, d0, s1, d1), 16B coalesced
    float4 dv0 = g_dv4[p.y];
    float4 dv1 = g_dv4[p.w];
    asm volatile(
        "red.global.add.v4.f32 [%0], {%1, %2, %3, %4};"
        :: "l"(&g_neigh4[p.x]), "f"(dv0.x), "f"(dv0.y), "f"(dv0.z), "f"(1.0f)
        : "memory");
    asm volatile(
        "red.global.add.v4.f32 [%0], {%1, %2, %3, %4};"
        :: "l"(&g_neigh4[p.z]), "f"(dv1.x), "f"(dv1.y), "f"(dv1.z), "f"(1.0f)
        : "memory");
}

// ---------------- K5: energy (4 pixels + 4 vertices per thread) --------------
__global__ void k_energy(const float4* __restrict__ hand4) {
    int i = blockIdx.x * blockDim.x + threadIdx.x;   // < 262144
    float local = 0.0f;

    float4 d = ((const float4*)g_depth)[i];
    float4 h = hand4[i];
    float e0 = d.x - h.x, e1 = d.y - h.y, e2 = d.z - h.z, e3 = d.w - h.w;
    local = e0 * e0 + e1 * e1 + e2 * e2 + e3 * e3;

    if (i < NV / 4) {
        #pragma unroll
        for (int k = 0; k < 4; k++) {
            float4 dv = g_dv4[4 * i + k];
            float4 nb = g_neigh4[4 * i + k];
            float dg = nb.w;
            float lx = dg * dv.x - nb.x;
            float ly = dg * dv.y - nb.y;
            float lz = dg * dv.z - nb.z;
            local += CREGU * (lx * lx + ly * ly + lz * lz);
        }
    }
    float b = block_reduce_f(local);
    if (threadIdx.x == 0) atomicAdd(&g_acc, (double)b);
}

// ---------------- K6: finalize ----------------------------------------------
__global__ void k_final(float* __restrict__ out) {
    out[0] = (float)g_acc;
}

// ---------------- launch -----------------------------------------------------
extern "C" void kernel_launch(void* const* d_in, const int* in_sizes, int n_in,
                              void* d_out, int out_size) {
    const float4* verts4 = (const float4*)d_in[0];
    const float4* vref4  = (const float4*)d_in[1];
    const float*  quat   = (const float*)d_in[2];
    const float*  trans  = (const float*)d_in[3];
    const float4* hand4  = (const float4*)d_in[4];
    const float*  intr   = (const float*)d_in[5];
    const float*  extr   = (const float*)d_in[6];
    const int4*   edges2 = (const int4*)d_in[7];
    float* out = (float*)d_out;

    const int B = 256;
    k_zero<<<1, 32>>>();
    k_init<<<(HW / 4) / B, B>>>(verts4, vref4);                  // 1024 blocks
    k_proj<<<(NV / 4 + B - 1) / B, B>>>(verts4, quat, trans, intr, extr);
    k_edge<<<(NE / 2 + B - 1) / B, B>>>(edges2);
    k_energy<<<(HW / 4) / B, B>>>(hand4);
    k_final<<<1, 1>>>(out);
}

// round 6
// speedup vs baseline: 3.0929x; 1.0762x over previous
#include <cuda_runtime.h>
#include <cuda_bf16.h>
#include <cstdint>

// Problem constants (match reference_code)
#define NV       1000000
#define NE       3000000
#define IMG_H    1024
#define IMG_W    1024
#define HW       (IMG_H * IMG_W)       // 1048576
#define MAX_DEPTH 10.0f
#define CREGU    2000.0f

// ---------------- scratch (device globals; zero-initialized at load) --------
__device__ float  g_depth[HW];        // 4 MB    scatter-min target
__device__ float4 g_dv4[NV];          // 16 MB   {dvx, dvy, dvz, 0}
__device__ float4 g_neigh4[NV];       // 16 MB   {nx, ny, nz, deg}
__device__ double g_sums[3];          // vertex component sums (zeroed by k_final)
__device__ double g_acc;              // total energy accumulator (zeroed by k_final)

// ---------------- float block reduce (shared) --------------------------------
__device__ __forceinline__ float block_reduce_f(float v) {
    __shared__ float sh[256];
    int t = threadIdx.x;
    sh[t] = v;
    __syncthreads();
    for (int s = blockDim.x >> 1; s > 32; s >>= 1) {
        if (t < s) sh[t] += sh[t + s];
        __syncthreads();
    }
    if (t < 32) {
        float x = sh[t] + sh[t + 32];
        #pragma unroll
        for (int o = 16; o > 0; o >>= 1)
            x += __shfl_down_sync(0xFFFFFFFFu, x, o);
        if (t == 0) sh[0] = x;
    }
    __syncthreads();
    return sh[0];
}

// ---------------- K1: depth fill + neigh zero + vertex mean partials ---------
// 262144 threads: 4 depth pixels each; threads < 250000 also read 4 vertices
// for the mean and zero their neigh4 slots.
__global__ void k_mean_fill(const float4* __restrict__ verts4) {
    int i = blockIdx.x * blockDim.x + threadIdx.x;   // < 262144
    ((float4*)g_depth)[i] = make_float4(MAX_DEPTH, MAX_DEPTH, MAX_DEPTH, MAX_DEPTH);

    float sx = 0.0f, sy = 0.0f, sz = 0.0f;
    if (i < NV / 4) {
        float4 a = verts4[3 * i + 0];   // v0.x v0.y v0.z v1.x
        float4 b = verts4[3 * i + 1];   // v1.y v1.z v2.x v2.y
        float4 c = verts4[3 * i + 2];   // v2.z v3.x v3.y v3.z
        sx = a.x + a.w + b.z + c.y;
        sy = a.y + b.x + b.w + c.z;
        sz = a.z + b.y + c.x + c.w;
        float4 z4 = make_float4(0.0f, 0.0f, 0.0f, 0.0f);
        g_neigh4[4 * i + 0] = z4;
        g_neigh4[4 * i + 1] = z4;
        g_neigh4[4 * i + 2] = z4;
        g_neigh4[4 * i + 3] = z4;
    }
    float bx = block_reduce_f(sx);
    __syncthreads();
    float by = block_reduce_f(sy);
    __syncthreads();
    float bz = block_reduce_f(sz);
    if (threadIdx.x == 0) {
        atomicAdd(&g_sums[0], (double)bx);
        atomicAdd(&g_sums[1], (double)by);
        atomicAdd(&g_sums[2], (double)bz);
    }
}

// ---------------- K2: dv compute + transform + project + scatter-min ---------
// 4 vertices per thread, 128-bit loads; warp-aggregated atomicMin.
__global__ void k_prep_proj(const float4* __restrict__ verts4,
                            const float4* __restrict__ vref4,
                            const float* __restrict__ quat,
                            const float* __restrict__ trans,
                            const float* __restrict__ intr,
                            const float* __restrict__ extr) {
    int i = blockIdx.x * blockDim.x + threadIdx.x;   // < 250000
    if (i >= NV / 4) return;

    float qx = quat[0], qy = quat[1], qz = quat[2], qw = quat[3];
    float qn = 1.0f / sqrtf(qx * qx + qy * qy + qz * qz + qw * qw);
    qx *= qn; qy *= qn; qz *= qn; qw *= qn;

    float mx = (float)(g_sums[0] / (double)NV);
    float my = (float)(g_sums[1] / (double)NV);
    float mz = (float)(g_sums[2] / (double)NV);

    float4 a = verts4[3 * i + 0];
    float4 b = verts4[3 * i + 1];
    float4 c = verts4[3 * i + 2];
    float4 ra = vref4[3 * i + 0];
    float4 rb = vref4[3 * i + 1];
    float4 rc = vref4[3 * i + 2];

    // dv = verts - vref (store once; consumed by k_edge / k_energy)
    g_dv4[4 * i + 0] = make_float4(a.x - ra.x, a.y - ra.y, a.z - ra.z, 0.0f);
    g_dv4[4 * i + 1] = make_float4(a.w - ra.w, b.x - rb.x, b.y - rb.y, 0.0f);
    g_dv4[4 * i + 2] = make_float4(b.z - rb.z, b.w - rb.w, c.x - rc.x, 0.0f);
    g_dv4[4 * i + 3] = make_float4(c.y - rc.y, c.z - rc.z, c.w - rc.w, 0.0f);

    float vxs[4] = {a.x, a.w, b.z, c.y};
    float vys[4] = {a.y, b.x, b.w, c.z};
    float vzs[4] = {a.z, b.y, c.x, c.w};

    unsigned amask = __activemask();   // stable: uniform early-exit above
    int lane = threadIdx.x & 31;

    #pragma unroll
    for (int k = 0; k < 4; k++) {
        float vx = vxs[k] - mx;
        float vy = vys[k] - my;
        float vz = vzs[k] - mz;

        // qrot: v + 2*(w*uv + uuv), uv = qv x v, uuv = qv x uv
        float uvx = qy * vz - qz * vy;
        float uvy = qz * vx - qx * vz;
        float uvz = qx * vy - qy * vx;
        float uuvx = qy * uvz - qz * uvy;
        float uuvy = qz * uvx - qx * uvz;
        float uuvz = qx * uvy - qy * uvx;
        float tx = vx + 2.0f * (qw * uvx + uuvx) + trans[0];
        float ty = vy + 2.0f * (qw * uvy + uuvy) + trans[1];
        float tz = vz + 2.0f * (qw * uvz + uuvz) + trans[2];

        // p_cam = E[:, :3] @ v_t + E[:, 3]   (extr row-major 3x4)
        float p0 = extr[0] * tx + extr[1] * ty + extr[2]  * tz + extr[3];
        float p1 = extr[4] * tx + extr[5] * ty + extr[6]  * tz + extr[7];
        float p2 = extr[8] * tx + extr[9] * ty + extr[10] * tz + extr[11];

        // proj = K @ p_cam (intr row-major 3x3)
        float pr0 = intr[0] * p0 + intr[1] * p1 + intr[2] * p2;
        float pr1 = intr[3] * p0 + intr[4] * p1 + intr[5] * p2;
        float pr2 = intr[6] * p0 + intr[7] * p1 + intr[8] * p2;

        float u = pr0 / pr2;
        float v = pr1 / pr2;

        float fx = rintf(u);                  // round half to even == jnp.round
        float fy = rintf(v);
        fx = fminf(fmaxf(fx, 0.0f), (float)(IMG_W - 1));
        fy = fminf(fmaxf(fy, 0.0f), (float)(IMG_H - 1));
        int xi = (int)fx;
        int yi = (int)fy;
        int flat = yi * IMG_W + xi;

        float zval = (p2 > 0.0f) ? p2 : MAX_DEPTH;   // DEPTH_SCALE = 1
        unsigned zb = (unsigned)__float_as_int(zval);  // zval > 0: order-preserving

        // warp-aggregate: one atomic per distinct pixel per warp
        unsigned grp = __match_any_sync(amask, flat);
        unsigned mn  = __reduce_min_sync(grp, zb);
        if (lane == __ffs(grp) - 1)
            atomicMin((int*)&g_depth[flat], (int)mn);
    }
}

// ---------------- K3: edge accumulation (2 edges/thread, v4 reductions) -----
__global__ void k_edge(const int4* __restrict__ edges2) {
    int e = blockIdx.x * blockDim.x + threadIdx.x;   // < NE/2
    if (e >= NE / 2) return;
    int4 p = edges2[e];                   // (s0, d0, s1, d1), 16B coalesced
    float4 dv0 = g_dv4[p.y];
    float4 dv1 = g_dv4[p.w];
    asm volatile(
        "red.global.add.v4.f32 [%0], {%1, %2, %3, %4};"
        :: "l"(&g_neigh4[p.x]), "f"(dv0.x), "f"(dv0.y), "f"(dv0.z), "f"(1.0f)
        : "memory");
    asm volatile(
        "red.global.add.v4.f32 [%0], {%1, %2, %3, %4};"
        :: "l"(&g_neigh4[p.z]), "f"(dv1.x), "f"(dv1.y), "f"(dv1.z), "f"(1.0f)
        : "memory");
}

// ---------------- K4: energy (4 pixels + 4 vertices per thread) --------------
__global__ void k_energy(const float4* __restrict__ hand4) {
    int i = blockIdx.x * blockDim.x + threadIdx.x;   // < 262144
    float local = 0.0f;

    float4 d = ((const float4*)g_depth)[i];
    float4 h = hand4[i];
    float e0 = d.x - h.x, e1 = d.y - h.y, e2 = d.z - h.z, e3 = d.w - h.w;
    local = e0 * e0 + e1 * e1 + e2 * e2 + e3 * e3;

    if (i < NV / 4) {
        #pragma unroll
        for (int k = 0; k < 4; k++) {
            float4 dv = g_dv4[4 * i + k];
            float4 nb = g_neigh4[4 * i + k];
            float dg = nb.w;
            float lx = dg * dv.x - nb.x;
            float ly = dg * dv.y - nb.y;
            float lz = dg * dv.z - nb.z;
            local += CREGU * (lx * lx + ly * ly + lz * lz);
        }
    }
    float b = block_reduce_f(local);
    if (threadIdx.x == 0) atomicAdd(&g_acc, (double)b);
}

// ---------------- K5: finalize + re-zero accumulators for next replay -------
__global__ void k_final(float* __restrict__ out) {
    out[0] = (float)g_acc;
    g_acc = 0.0;
    g_sums[0] = 0.0; g_sums[1] = 0.0; g_sums[2] = 0.0;
}

// ---------------- launch -----------------------------------------------------
extern "C" void kernel_launch(void* const* d_in, const int* in_sizes, int n_in,
                              void* d_out, int out_size) {
    const float4* verts4 = (const float4*)d_in[0];
    const float4* vref4  = (const float4*)d_in[1];
    const float*  quat   = (const float*)d_in[2];
    const float*  trans  = (const float*)d_in[3];
    const float4* hand4  = (const float4*)d_in[4];
    const float*  intr   = (const float*)d_in[5];
    const float*  extr   = (const float*)d_in[6];
    const int4*   edges2 = (const int4*)d_in[7];
    float* out = (float*)d_out;

    const int B = 256;
    k_mean_fill<<<(HW / 4) / B, B>>>(verts4);                    // 1024 blocks
    k_prep_proj<<<(NV / 4 + B - 1) / B, B>>>(verts4, vref4, quat, trans, intr, extr);
    k_edge<<<(NE / 2 + B - 1) / B, B>>>(edges2);
    k_energy<<<(HW / 4) / B, B>>>(hand4);
    k_final<<<1, 1>>>(out);
}